// round 9
// baseline (speedup 1.0000x reference)
#include <cuda_runtime.h>
#include <cuda_bf16.h>
#include <math.h>
#include <stdint.h>

#define DMODEL 1024
#define NHEAD  16
#define FFDIM  4096
#define ROWS   4096      // B*S
#define SEQ    2048
#define QKVW   3072      // packed qkv row width
#define LN_EPS 1e-6f

typedef __nv_bfloat16 bf16;

// ---------------- scratch (no allocation allowed) ----------------
__device__ float g_x1[ROWS * DMODEL];

__device__ bf16 g_lnh  [ROWS * DMODEL],  g_lnl  [ROWS * DMODEL];
__device__ bf16 g_qkvh [ROWS * QKVW],    g_qkvl [ROWS * QKVW];     // [row][q|k|v]
__device__ bf16 g_vth  [ROWS * DMODEL],  g_vtl  [ROWS * DMODEL];   // [b,h,d,s]
__device__ bf16 g_atth [ROWS * DMODEL],  g_attl [ROWS * DMODEL];
__device__ bf16 g_ffh  [ROWS * FFDIM],   g_ffl  [ROWS * FFDIM];
__device__ bf16 g_wqkvh[QKVW * DMODEL],  g_wqkvl[QKVW * DMODEL];   // [n][k]
__device__ bf16 g_woh  [DMODEL * DMODEL],g_wol  [DMODEL * DMODEL];
__device__ bf16 g_w1h  [DMODEL * FFDIM], g_w1l  [DMODEL * FFDIM];
__device__ bf16 g_w2h  [FFDIM * DMODEL], g_w2l  [FFDIM * DMODEL];

__device__ __forceinline__ void split2(float f, bf16& h, bf16& l) {
    h = __float2bfloat16_rn(f);
    l = __float2bfloat16_rn(f - __bfloat162float(h));
}
__device__ __forceinline__ unsigned packbf2(float a, float b) {
    __nv_bfloat162 t;
    t.x = __float2bfloat16_rn(a);
    t.y = __float2bfloat16_rn(b);
    return *(unsigned*)&t;
}
__device__ __forceinline__ unsigned packlo2(float a, float b) {
    __nv_bfloat162 t;
    t.x = __float2bfloat16_rn(a - __bfloat162float(__float2bfloat16_rn(a)));
    t.y = __float2bfloat16_rn(b - __bfloat162float(__float2bfloat16_rn(b)));
    return *(unsigned*)&t;
}

// ---------------- LayerNorm -> bf16 hi/lo split output ----------------
__global__ void ln_split_kernel(const float* __restrict__ x,
                                const float* __restrict__ gamma,
                                const float* __restrict__ beta,
                                bf16* __restrict__ oh, bf16* __restrict__ ol) {
    int row = blockIdx.x;
    int t = threadIdx.x;
    const float4* xr = (const float4*)(x + (size_t)row * DMODEL);
    float4 v = xr[t];
    float s  = v.x + v.y + v.z + v.w;
    float ss = v.x * v.x + v.y * v.y + v.z * v.z + v.w * v.w;
    #pragma unroll
    for (int o = 16; o > 0; o >>= 1) {
        s  += __shfl_xor_sync(0xFFFFFFFFu, s,  o);
        ss += __shfl_xor_sync(0xFFFFFFFFu, ss, o);
    }
    __shared__ float rs[8], rss[8];
    int wid = t >> 5, lid = t & 31;
    if (lid == 0) { rs[wid] = s; rss[wid] = ss; }
    __syncthreads();
    s = 0.f; ss = 0.f;
    #pragma unroll
    for (int i = 0; i < 8; i++) { s += rs[i]; ss += rss[i]; }
    float mean = s * (1.0f / DMODEL);
    float var  = (ss - (float)DMODEL * mean * mean) * (1.0f / (DMODEL - 1));
    float inv  = 1.0f / (sqrtf(fmaxf(var, 0.0f)) + LN_EPS);
    const float4 gg = ((const float4*)gamma)[t];
    const float4 bb = ((const float4*)beta)[t];
    float o4[4];
    o4[0] = gg.x * (v.x - mean) * inv + bb.x;
    o4[1] = gg.y * (v.y - mean) * inv + bb.y;
    o4[2] = gg.z * (v.z - mean) * inv + bb.z;
    o4[3] = gg.w * (v.w - mean) * inv + bb.w;
    bf16 hh[4], ll[4];
    #pragma unroll
    for (int j = 0; j < 4; j++) split2(o4[j], hh[j], ll[j]);
    size_t base = (size_t)row * DMODEL + t * 4;
    *(uint2*)(oh + base) = *(uint2*)hh;
    *(uint2*)(ol + base) = *(uint2*)ll;
}

// ---------------- Weight transpose + split: [K,N] fp32 -> [N][K] bf16 hi/lo ----
__global__ void wsplit_tr_kernel(const float* __restrict__ W,
                                 bf16* __restrict__ Th, bf16* __restrict__ Tl,
                                 int K, int N) {
    __shared__ float t[32][33];
    int n0 = blockIdx.x * 32, k0 = blockIdx.y * 32;
    int tx = threadIdx.x, ty = threadIdx.y;   // 32 x 8
    #pragma unroll
    for (int i = 0; i < 4; i++)
        t[ty + 8 * i][tx] = W[(size_t)(k0 + ty + 8 * i) * N + n0 + tx];
    __syncthreads();
    #pragma unroll
    for (int i = 0; i < 4; i++) {
        float f = t[tx][ty + 8 * i];
        bf16 h, l; split2(f, h, l);
        size_t o = (size_t)(n0 + ty + 8 * i) * K + k0 + tx;
        Th[o] = h; Tl[o] = l;
    }
}

// ---------------- V transpose: packed qkv [row][3072] col 2048+ -> [b,h,d,s] ----
__global__ void vtr_kernel(const bf16* __restrict__ V, bf16* __restrict__ Vt) {
    __shared__ bf16 t[32][33];
    int s0 = blockIdx.x * 32, d0 = blockIdx.y * 32, z = blockIdx.z;  // z = b*16+h
    int bq = z >> 4, hq = z & 15;
    int tx = threadIdx.x, ty = threadIdx.y;    // 32 x 8
    #pragma unroll
    for (int i = 0; i < 4; i++)
        t[ty + 8 * i][tx] = V[(size_t)(bq * SEQ + s0 + ty + 8 * i) * QKVW + 2048 + hq * 64 + d0 + tx];
    __syncthreads();
    #pragma unroll
    for (int i = 0; i < 4; i++)
        Vt[(size_t)(z * 64 + d0 + ty + 8 * i) * SEQ + s0 + tx] = t[tx][ty + 8 * i];
}

// ---------------- common helpers ----------------
__device__ __forceinline__ void cpa16(uint32_t d, const void* s) {
    asm volatile("cp.async.cg.shared.global [%0], [%1], 16;" :: "r"(d), "l"(s));
}
__device__ __forceinline__ void cpcommit() {
    asm volatile("cp.async.commit_group;");
}
template<int W> __device__ __forceinline__ void cpwait() {
    asm volatile("cp.async.wait_group %0;" :: "n"(W));
}
__device__ __forceinline__ void mma16816(float c[4], const unsigned a[4], const unsigned b[2]) {
    asm volatile(
        "mma.sync.aligned.m16n8k16.row.col.f32.bf16.bf16.f32 "
        "{%0,%1,%2,%3}, {%4,%5,%6,%7}, {%8,%9}, {%0,%1,%2,%3};\n"
        : "+f"(c[0]), "+f"(c[1]), "+f"(c[2]), "+f"(c[3])
        : "r"(a[0]), "r"(a[1]), "r"(a[2]), "r"(a[3]), "r"(b[0]), "r"(b[1]));
}

// ---------------- Tensor-core GEMM: BM128 x BN64, 2-stage, 2 CTAs/SM ----------
// A(hi/lo): [M][K] bf16 rm. B(hi/lo): [N][K] bf16 (k-contiguous). C = act(A@B^T)+res.
#define BM 128
#define BN 64
#define BK 32
#define SKP 40                      // smem row stride in halves (80 B)
#define TILE_A (128 * SKP * 2)      // 10240 B
#define TILE_BB (64 * SKP * 2)      // 5120 B
#define STAGE_B (2 * TILE_A + 2 * TILE_BB)   // 30720 B

__device__ __forceinline__ void fill_stage(uint32_t sb,
        const bf16* __restrict__ Agh, const bf16* __restrict__ Agl,
        const bf16* __restrict__ Bgh, const bf16* __restrict__ Bgl,
        int row0, int col0, int k0, int K, int tid) {
    // A: 128 rows x 64B
    {
        int r  = tid >> 1;
        int kb = (tid & 1) * 32;
        size_t aoff = ((size_t)(row0 + r) * K + k0) * 2 + kb;
        uint32_t dst = sb + (uint32_t)r * (SKP * 2) + kb;
        cpa16(dst,               (const char*)Agh + aoff);
        cpa16(dst + 16,          (const char*)Agh + aoff + 16);
        cpa16(dst + TILE_A,      (const char*)Agl + aoff);
        cpa16(dst + TILE_A + 16, (const char*)Agl + aoff + 16);
    }
    // B: 64 rows x 64B
    {
        int r  = tid >> 2;
        int kb = (tid & 3) * 16;
        size_t boff = ((size_t)(col0 + r) * K + k0) * 2 + kb;
        uint32_t dst = sb + 2 * TILE_A + (uint32_t)r * (SKP * 2) + kb;
        cpa16(dst,           (const char*)Bgh + boff);
        cpa16(dst + TILE_BB, (const char*)Bgl + boff);
    }
}

template<bool RELU, bool SPLIT>
__global__ __launch_bounds__(256, 2)
void gemm_mma(const bf16* __restrict__ Agh, const bf16* __restrict__ Agl,
              const bf16* __restrict__ Bgh, const bf16* __restrict__ Bgl,
              const float* __restrict__ bias, const float* __restrict__ res,
              float* __restrict__ C, bf16* __restrict__ Ch, bf16* __restrict__ Cl,
              int M, int N, int K) {
    extern __shared__ bf16 smem[];
    uint32_t sbase = (uint32_t)__cvta_generic_to_shared(smem);
    int tid = threadIdx.x, lane = tid & 31, warp = tid >> 5;
    int g = lane >> 2, tig = lane & 3;
    int m_base = (warp & 3) * 32, n_base = (warp >> 2) * 32;
    int row0 = blockIdx.y * BM, col0 = blockIdx.x * BN;

    float acc[2][4][4];
    #pragma unroll
    for (int mi = 0; mi < 2; mi++)
        #pragma unroll
        for (int ni = 0; ni < 4; ni++)
            #pragma unroll
            for (int r = 0; r < 4; r++) acc[mi][ni][r] = 0.0f;

    int NIT = K >> 5;
    fill_stage(sbase, Agh, Agl, Bgh, Bgl, row0, col0, 0, K, tid);
    cpcommit();

    for (int it = 0; it < NIT; ++it) {
        if (it + 1 < NIT) {
            fill_stage(sbase + ((it + 1) & 1) * STAGE_B, Agh, Agl, Bgh, Bgl,
                       row0, col0, (it + 1) << 5, K, tid);
            cpcommit();
            cpwait<1>();
        } else {
            cpwait<0>();
        }
        __syncthreads();

        const bf16* st  = smem + (it & 1) * (STAGE_B / 2);
        const bf16* Ahs = st;
        const bf16* Als = st + TILE_A / 2;
        const bf16* Bhs = st + TILE_A;
        const bf16* Bls = st + TILE_A + TILE_BB / 2;

        #pragma unroll
        for (int ks = 0; ks < 2; ks++) {
            int kk = ks * 16;
            unsigned a_h[2][4], a_l[2][4], b_h[4][2], b_l[4][2];
            #pragma unroll
            for (int mi = 0; mi < 2; mi++) {
                int r = m_base + mi * 16 + g;
                int base = r * SKP + kk + 2 * tig;
                a_h[mi][0] = *(const unsigned*)(Ahs + base);
                a_h[mi][1] = *(const unsigned*)(Ahs + base + 8 * SKP);
                a_h[mi][2] = *(const unsigned*)(Ahs + base + 8);
                a_h[mi][3] = *(const unsigned*)(Ahs + base + 8 * SKP + 8);
                a_l[mi][0] = *(const unsigned*)(Als + base);
                a_l[mi][1] = *(const unsigned*)(Als + base + 8 * SKP);
                a_l[mi][2] = *(const unsigned*)(Als + base + 8);
                a_l[mi][3] = *(const unsigned*)(Als + base + 8 * SKP + 8);
            }
            #pragma unroll
            for (int ni = 0; ni < 4; ni++) {
                int n = n_base + ni * 8 + g;
                int base = n * SKP + kk + 2 * tig;
                b_h[ni][0] = *(const unsigned*)(Bhs + base);
                b_h[ni][1] = *(const unsigned*)(Bhs + base + 8);
                b_l[ni][0] = *(const unsigned*)(Bls + base);
                b_l[ni][1] = *(const unsigned*)(Bls + base + 8);
            }
            #pragma unroll
            for (int mi = 0; mi < 2; mi++)
                #pragma unroll
                for (int ni = 0; ni < 4; ni++) {
                    mma16816(acc[mi][ni], a_h[mi], b_h[ni]);
                    mma16816(acc[mi][ni], a_h[mi], b_l[ni]);
                    mma16816(acc[mi][ni], a_l[mi], b_h[ni]);
                }
        }
        __syncthreads();
    }

    #pragma unroll
    for (int mi = 0; mi < 2; mi++) {
        #pragma unroll
        for (int ni = 0; ni < 4; ni++) {
            int r = row0 + m_base + mi * 16 + g;
            int c = col0 + n_base + ni * 8 + 2 * tig;
            float2 b2 = make_float2(0.f, 0.f);
            if (bias) b2 = *(const float2*)(bias + c);
            float2 v0, v1;
            v0.x = acc[mi][ni][0] + b2.x; v0.y = acc[mi][ni][1] + b2.y;
            v1.x = acc[mi][ni][2] + b2.x; v1.y = acc[mi][ni][3] + b2.y;
            if (RELU) {
                v0.x = fmaxf(v0.x, 0.f); v0.y = fmaxf(v0.y, 0.f);
                v1.x = fmaxf(v1.x, 0.f); v1.y = fmaxf(v1.y, 0.f);
            }
            if (res) {
                float2 r0 = *(const float2*)(res + (size_t)r * N + c);
                float2 r1 = *(const float2*)(res + (size_t)(r + 8) * N + c);
                v0.x += r0.x; v0.y += r0.y; v1.x += r1.x; v1.y += r1.y;
            }
            if (SPLIT) {
                *(unsigned*)(Ch + (size_t)r * N + c)       = packbf2(v0.x, v0.y);
                *(unsigned*)(Ch + (size_t)(r + 8) * N + c) = packbf2(v1.x, v1.y);
                *(unsigned*)(Cl + (size_t)r * N + c)       = packlo2(v0.x, v0.y);
                *(unsigned*)(Cl + (size_t)(r + 8) * N + c) = packlo2(v1.x, v1.y);
            } else {
                *(float2*)(C + (size_t)r * N + c)       = v0;
                *(float2*)(C + (size_t)(r + 8) * N + c) = v1;
            }
        }
    }
}

// ---------------- MMA flash attention (R6 structure; packed QKV input) ----------
#define AQT 128
#define ASK 72                    // smem row stride in halves
#define AROWB (ASK * 2)
#define ATILE (64 * AROWB)
#define ASTAGE (4 * ATILE)

__device__ __forceinline__ void attn_fill(uint32_t sb, int stage,
        const bf16* __restrict__ QKVh, const bf16* __restrict__ QKVl,
        const bf16* __restrict__ Vth, const bf16* __restrict__ Vtl,
        int b, int h, int kt, int tid) {
    int r  = tid >> 2;
    int q4 = (tid & 3) * 32;
    size_t koff = ((size_t)(b * SEQ + kt * 64 + r) * QKVW + 1024 + h * 64) * 2 + q4;
    size_t voff = ((size_t)((b * NHEAD + h) * 64 + r) * SEQ + kt * 64) * 2 + q4;
    uint32_t d = sb + stage * ASTAGE + (uint32_t)r * AROWB + q4;
    cpa16(d,                  (const char*)QKVh + koff);
    cpa16(d + 16,             (const char*)QKVh + koff + 16);
    cpa16(d + ATILE,          (const char*)QKVl + koff);
    cpa16(d + ATILE + 16,     (const char*)QKVl + koff + 16);
    cpa16(d + 2 * ATILE,      (const char*)Vth + voff);
    cpa16(d + 2 * ATILE + 16, (const char*)Vth + voff + 16);
    cpa16(d + 3 * ATILE,      (const char*)Vtl + voff);
    cpa16(d + 3 * ATILE + 16, (const char*)Vtl + voff + 16);
}

__global__ __launch_bounds__(256)
void attn_mma_kernel(const bf16* __restrict__ QKVh, const bf16* __restrict__ QKVl,
                     const bf16* __restrict__ Vth, const bf16* __restrict__ Vtl,
                     bf16* __restrict__ Oh, bf16* __restrict__ Ol) {
    extern __shared__ char smraw[];
    uint32_t sb = (uint32_t)__cvta_generic_to_shared(smraw);
    int b = blockIdx.z, h = blockIdx.y, qb = blockIdx.x * AQT;
    int tid = threadIdx.x, lane = tid & 31, warp = tid >> 5;
    int g = lane >> 2, tig = lane & 3;

    {   // stage Q tile (128 x 64) hi/lo from packed cols [0,1024)
        int r = tid >> 1;
        int half = (tid & 1) * 64;
        size_t qoff = ((size_t)(b * SEQ + qb + r) * QKVW + h * 64) * 2 + half;
        uint32_t d0 = sb + (uint32_t)r * AROWB + half;
        #pragma unroll
        for (int i = 0; i < 4; i++) cpa16(d0 + 16 * i, (const char*)QKVh + qoff + 16 * i);
        uint32_t d1 = sb + 2 * ATILE + (uint32_t)r * AROWB + half;
        #pragma unroll
        for (int i = 0; i < 4; i++) cpa16(d1 + 16 * i, (const char*)QKVl + qoff + 16 * i);
    }
    cpcommit(); cpwait<0>(); __syncthreads();

    unsigned qfh[4][4], qfl[4][4];
    {
        const bf16* Qs_h = (const bf16*)smraw;
        const bf16* Qs_l = (const bf16*)(smraw + 2 * ATILE);
        int mrow = warp * 16 + g;
        #pragma unroll
        for (int ks = 0; ks < 4; ks++) {
            int base = mrow * ASK + ks * 16 + 2 * tig;
            qfh[ks][0] = *(const unsigned*)(Qs_h + base);
            qfh[ks][1] = *(const unsigned*)(Qs_h + base + 8 * ASK);
            qfh[ks][2] = *(const unsigned*)(Qs_h + base + 8);
            qfh[ks][3] = *(const unsigned*)(Qs_h + base + 8 * ASK + 8);
            qfl[ks][0] = *(const unsigned*)(Qs_l + base);
            qfl[ks][1] = *(const unsigned*)(Qs_l + base + 8 * ASK);
            qfl[ks][2] = *(const unsigned*)(Qs_l + base + 8);
            qfl[ks][3] = *(const unsigned*)(Qs_l + base + 8 * ASK + 8);
        }
    }
    __syncthreads();

    float oacc[8][4];
    #pragma unroll
    for (int nf = 0; nf < 8; nf++)
        #pragma unroll
        for (int c = 0; c < 4; c++) oacc[nf][c] = 0.f;
    float mrow[2] = {-1e30f, -1e30f}, lrow[2] = {0.f, 0.f};

    const int NKT = SEQ / 64;
    attn_fill(sb, 0, QKVh, QKVl, Vth, Vtl, b, h, 0, tid);
    cpcommit();

    for (int kt = 0; kt < NKT; kt++) {
        if (kt + 1 < NKT) {
            attn_fill(sb, (kt + 1) & 1, QKVh, QKVl, Vth, Vtl, b, h, kt + 1, tid);
            cpcommit();
            cpwait<1>();
        } else {
            cpwait<0>();
        }
        __syncthreads();

        const bf16* st   = (const bf16*)(smraw + (kt & 1) * ASTAGE);
        const bf16* Ks_h = st;
        const bf16* Ks_l = st + ATILE / 2;
        const bf16* Vs_h = st + 2 * (ATILE / 2);
        const bf16* Vs_l = st + 3 * (ATILE / 2);

        float sacc[8][4];
        #pragma unroll
        for (int nf = 0; nf < 8; nf++)
            #pragma unroll
            for (int c = 0; c < 4; c++) sacc[nf][c] = 0.f;
        #pragma unroll
        for (int ks = 0; ks < 4; ks++) {
            #pragma unroll
            for (int nf = 0; nf < 8; nf++) {
                int n = nf * 8 + g;
                int base = n * ASK + ks * 16 + 2 * tig;
                unsigned bh2[2], bl2[2];
                bh2[0] = *(const unsigned*)(Ks_h + base);
                bh2[1] = *(const unsigned*)(Ks_h + base + 8);
                bl2[0] = *(const unsigned*)(Ks_l + base);
                bl2[1] = *(const unsigned*)(Ks_l + base + 8);
                mma16816(sacc[nf], qfh[ks], bh2);
                mma16816(sacc[nf], qfh[ks], bl2);
                mma16816(sacc[nf], qfl[ks], bh2);
            }
        }

        #pragma unroll
        for (int nf = 0; nf < 8; nf++)
            #pragma unroll
            for (int c = 0; c < 4; c++) sacc[nf][c] *= 0.125f;

        #pragma unroll
        for (int rr = 0; rr < 2; rr++) {
            float rm = -1e30f;
            #pragma unroll
            for (int nf = 0; nf < 8; nf++)
                rm = fmaxf(rm, fmaxf(sacc[nf][2 * rr], sacc[nf][2 * rr + 1]));
            rm = fmaxf(rm, __shfl_xor_sync(0xFFFFFFFFu, rm, 1));
            rm = fmaxf(rm, __shfl_xor_sync(0xFFFFFFFFu, rm, 2));
            float mn = fmaxf(mrow[rr], rm);
            float al = __expf(mrow[rr] - mn);
            mrow[rr] = mn;
            float rs = 0.f;
            #pragma unroll
            for (int nf = 0; nf < 8; nf++) {
                sacc[nf][2 * rr]     = __expf(sacc[nf][2 * rr]     - mn);
                sacc[nf][2 * rr + 1] = __expf(sacc[nf][2 * rr + 1] - mn);
                rs += sacc[nf][2 * rr] + sacc[nf][2 * rr + 1];
            }
            rs += __shfl_xor_sync(0xFFFFFFFFu, rs, 1);
            rs += __shfl_xor_sync(0xFFFFFFFFu, rs, 2);
            lrow[rr] = lrow[rr] * al + rs;
            #pragma unroll
            for (int nf = 0; nf < 8; nf++) {
                oacc[nf][2 * rr]     *= al;
                oacc[nf][2 * rr + 1] *= al;
            }
        }

        #pragma unroll
        for (int ks = 0; ks < 4; ks++) {
            unsigned ph2[4], pl2[4];
            ph2[0] = packbf2(sacc[2 * ks][0],     sacc[2 * ks][1]);
            ph2[1] = packbf2(sacc[2 * ks][2],     sacc[2 * ks][3]);
            ph2[2] = packbf2(sacc[2 * ks + 1][0], sacc[2 * ks + 1][1]);
            ph2[3] = packbf2(sacc[2 * ks + 1][2], sacc[2 * ks + 1][3]);
            pl2[0] = packlo2(sacc[2 * ks][0],     sacc[2 * ks][1]);
            pl2[1] = packlo2(sacc[2 * ks][2],     sacc[2 * ks][3]);
            pl2[2] = packlo2(sacc[2 * ks + 1][0], sacc[2 * ks + 1][1]);
            pl2[3] = packlo2(sacc[2 * ks + 1][2], sacc[2 * ks + 1][3]);
            #pragma unroll
            for (int nf = 0; nf < 8; nf++) {
                int n = nf * 8 + g;
                int base = n * ASK + ks * 16 + 2 * tig;
                unsigned vh2[2], vl2[2];
                vh2[0] = *(const unsigned*)(Vs_h + base);
                vh2[1] = *(const unsigned*)(Vs_h + base + 8);
                vl2[0] = *(const unsigned*)(Vs_l + base);
                vl2[1] = *(const unsigned*)(Vs_l + base + 8);
                mma16816(oacc[nf], ph2, vh2);
                mma16816(oacc[nf], ph2, vl2);
                mma16816(oacc[nf], pl2, vh2);
            }
        }
        __syncthreads();
    }

    #pragma unroll
    for (int rr = 0; rr < 2; rr++) {
        float inv = 1.0f / lrow[rr];
        size_t r_glob = (size_t)(b * SEQ + qb + warp * 16 + g + rr * 8);
        #pragma unroll
        for (int nf = 0; nf < 8; nf++) {
            int col = h * 64 + nf * 8 + 2 * tig;
            float o0 = oacc[nf][2 * rr] * inv;
            float o1 = oacc[nf][2 * rr + 1] * inv;
            *(unsigned*)(Oh + r_glob * DMODEL + col) = packbf2(o0, o1);
            *(unsigned*)(Ol + r_glob * DMODEL + col) = packlo2(o0, o1);
        }
    }
}

// ---------------- launch ----------------
extern "C" void kernel_launch(void* const* d_in, const int* in_sizes, int n_in,
                              void* d_out, int out_size) {
    const float* x   = (const float*)d_in[0];
    const float* w_q = (const float*)d_in[1];
    const float* w_k = (const float*)d_in[2];
    const float* w_v = (const float*)d_in[3];
    const float* w_o = (const float*)d_in[4];
    const float* w1  = (const float*)d_in[5];
    const float* b1  = (const float*)d_in[6];
    const float* w2  = (const float*)d_in[7];
    const float* b2  = (const float*)d_in[8];
    const float* g1  = (const float*)d_in[9];
    const float* be1 = (const float*)d_in[10];
    const float* g2  = (const float*)d_in[11];
    const float* be2 = (const float*)d_in[12];
    float* out = (float*)d_out;

    float *x1;
    bf16 *lnh, *lnl, *qkvh, *qkvl, *vth, *vtl, *atth, *attl, *ffh, *ffl;
    bf16 *wqkvh, *wqkvl, *woh, *wol, *w1h, *w1l, *w2h, *w2l;
    cudaGetSymbolAddress((void**)&x1,    g_x1);
    cudaGetSymbolAddress((void**)&lnh,   g_lnh);   cudaGetSymbolAddress((void**)&lnl,   g_lnl);
    cudaGetSymbolAddress((void**)&qkvh,  g_qkvh);  cudaGetSymbolAddress((void**)&qkvl,  g_qkvl);
    cudaGetSymbolAddress((void**)&vth,   g_vth);   cudaGetSymbolAddress((void**)&vtl,   g_vtl);
    cudaGetSymbolAddress((void**)&atth,  g_atth);  cudaGetSymbolAddress((void**)&attl,  g_attl);
    cudaGetSymbolAddress((void**)&ffh,   g_ffh);   cudaGetSymbolAddress((void**)&ffl,   g_ffl);
    cudaGetSymbolAddress((void**)&wqkvh, g_wqkvh); cudaGetSymbolAddress((void**)&wqkvl, g_wqkvl);
    cudaGetSymbolAddress((void**)&woh,   g_woh);   cudaGetSymbolAddress((void**)&wol,   g_wol);
    cudaGetSymbolAddress((void**)&w1h,   g_w1h);   cudaGetSymbolAddress((void**)&w1l,   g_w1l);
    cudaGetSymbolAddress((void**)&w2h,   g_w2h);   cudaGetSymbolAddress((void**)&w2l,   g_w2l);

    const int gemm_smem = 2 * STAGE_B;   // 61440 B -> 2 CTAs/SM
    cudaFuncSetAttribute(gemm_mma<false, false>, cudaFuncAttributeMaxDynamicSharedMemorySize, gemm_smem);
    cudaFuncSetAttribute(gemm_mma<false, true >, cudaFuncAttributeMaxDynamicSharedMemorySize, gemm_smem);
    cudaFuncSetAttribute(gemm_mma<true,  true >, cudaFuncAttributeMaxDynamicSharedMemorySize, gemm_smem);
    const int attn_smem = 2 * ASTAGE;
    cudaFuncSetAttribute(attn_mma_kernel, cudaFuncAttributeMaxDynamicSharedMemorySize, attn_smem);

    dim3 wb(32, 8);
    dim3 gQKV (QKVW / BN, ROWS / BM);    // 48 x 32
    dim3 gProj(DMODEL / BN, ROWS / BM);  // 16 x 32
    dim3 gFF1 (FFDIM / BN, ROWS / BM);   // 64 x 32

    // launches 0-3: qkv weight splits into packed [3072][1024] + w_o
    wsplit_tr_kernel<<<dim3(DMODEL/32, DMODEL/32), wb>>>(w_q, wqkvh,                 wqkvl,                 DMODEL, DMODEL);
    wsplit_tr_kernel<<<dim3(DMODEL/32, DMODEL/32), wb>>>(w_k, wqkvh + 1024 * DMODEL, wqkvl + 1024 * DMODEL, DMODEL, DMODEL);
    wsplit_tr_kernel<<<dim3(DMODEL/32, DMODEL/32), wb>>>(w_v, wqkvh + 2048 * DMODEL, wqkvl + 2048 * DMODEL, DMODEL, DMODEL);
    // launch 4: LN1
    ln_split_kernel<<<ROWS, 256>>>(x, g1, be1, lnh, lnl);
    // launch 5: fused QKV GEMM  (<- ncu -s 5 profiles this)
    gemm_mma<false,true><<<gQKV, 256, gemm_smem>>>(lnh, lnl, wqkvh, wqkvl, nullptr, nullptr, nullptr, qkvh, qkvl, ROWS, QKVW, DMODEL);
    // remaining weight preps (independent)
    wsplit_tr_kernel<<<dim3(DMODEL/32, DMODEL/32), wb>>>(w_o, woh, wol, DMODEL, DMODEL);
    wsplit_tr_kernel<<<dim3(FFDIM/32,  DMODEL/32), wb>>>(w1,  w1h, w1l, DMODEL, FFDIM);
    wsplit_tr_kernel<<<dim3(DMODEL/32, FFDIM/32),  wb>>>(w2,  w2h, w2l, FFDIM, DMODEL);
    // V transpose to [b,h,d,s] (reads packed v block)
    vtr_kernel<<<dim3(SEQ/32, 2, 32), wb>>>(qkvh, vth);
    vtr_kernel<<<dim3(SEQ/32, 2, 32), wb>>>(qkvl, vtl);
    // MMA attention -> split output
    attn_mma_kernel<<<dim3(SEQ/AQT, NHEAD, 2), 256, attn_smem>>>(qkvh, qkvl, vth, vtl, atth, attl);
    // output projection + residual (fp32 out)
    gemm_mma<false,false><<<gProj, 256, gemm_smem>>>(atth, attl, woh, wol, nullptr, x, x1, nullptr, nullptr, ROWS, DMODEL, DMODEL);
    // LN2 -> split
    ln_split_kernel<<<ROWS, 256>>>(x1, g2, be2, lnh, lnl);
    // FFN
    gemm_mma<true, true ><<<gFF1,  256, gemm_smem>>>(lnh, lnl, w1h, w1l, b1, nullptr, nullptr, ffh, ffl, ROWS, FFDIM, DMODEL);
    gemm_mma<false,false><<<gProj, 256, gemm_smem>>>(ffh, ffl, w2h, w2l, b2, x1, out, nullptr, nullptr, ROWS, DMODEL, FFDIM);
}

// round 10
// speedup vs baseline: 1.5561x; 1.5561x over previous
#include <cuda_runtime.h>
#include <cuda_bf16.h>
#include <math.h>
#include <stdint.h>

#define DMODEL 1024
#define NHEAD  16
#define FFDIM  4096
#define ROWS   4096      // B*S
#define SEQ    2048
#define LN_EPS 1e-6f

typedef __nv_bfloat16 bf16;

// ---------------- scratch (no allocation allowed) ----------------
__device__ float g_x1[ROWS * DMODEL];

__device__ bf16 g_lnh [ROWS * DMODEL],   g_lnl [ROWS * DMODEL];
__device__ bf16 g_qh  [ROWS * DMODEL],   g_ql  [ROWS * DMODEL];
__device__ bf16 g_kh  [ROWS * DMODEL],   g_kl  [ROWS * DMODEL];
__device__ bf16 g_vh  [ROWS * DMODEL],   g_vl  [ROWS * DMODEL];
__device__ bf16 g_vth [ROWS * DMODEL],   g_vtl [ROWS * DMODEL];   // [b,h,d,s]
__device__ bf16 g_atth[ROWS * DMODEL],   g_attl[ROWS * DMODEL];
__device__ bf16 g_ffh [ROWS * FFDIM],    g_ffl [ROWS * FFDIM];
__device__ bf16 g_wqh [DMODEL * DMODEL], g_wql [DMODEL * DMODEL];
__device__ bf16 g_wkh [DMODEL * DMODEL], g_wkl [DMODEL * DMODEL];
__device__ bf16 g_wvh [DMODEL * DMODEL], g_wvl [DMODEL * DMODEL];
__device__ bf16 g_woh [DMODEL * DMODEL], g_wol [DMODEL * DMODEL];
__device__ bf16 g_w1h [DMODEL * FFDIM],  g_w1l [DMODEL * FFDIM];
__device__ bf16 g_w2h [FFDIM * DMODEL],  g_w2l [FFDIM * DMODEL];

__device__ __forceinline__ void split2(float f, bf16& h, bf16& l) {
    h = __float2bfloat16_rn(f);
    l = __float2bfloat16_rn(f - __bfloat162float(h));
}
__device__ __forceinline__ unsigned packbf2(float a, float b) {
    __nv_bfloat162 t;
    t.x = __float2bfloat16_rn(a);
    t.y = __float2bfloat16_rn(b);
    return *(unsigned*)&t;
}
__device__ __forceinline__ unsigned packlo2(float a, float b) {
    __nv_bfloat162 t;
    t.x = __float2bfloat16_rn(a - __bfloat162float(__float2bfloat16_rn(a)));
    t.y = __float2bfloat16_rn(b - __bfloat162float(__float2bfloat16_rn(b)));
    return *(unsigned*)&t;
}

// ---------------- LayerNorm -> bf16 hi/lo split output ----------------
__global__ void ln_split_kernel(const float* __restrict__ x,
                                const float* __restrict__ gamma,
                                const float* __restrict__ beta,
                                bf16* __restrict__ oh, bf16* __restrict__ ol) {
    int row = blockIdx.x;
    int t = threadIdx.x;
    const float4* xr = (const float4*)(x + (size_t)row * DMODEL);
    float4 v = xr[t];
    float s  = v.x + v.y + v.z + v.w;
    float ss = v.x * v.x + v.y * v.y + v.z * v.z + v.w * v.w;
    #pragma unroll
    for (int o = 16; o > 0; o >>= 1) {
        s  += __shfl_xor_sync(0xFFFFFFFFu, s,  o);
        ss += __shfl_xor_sync(0xFFFFFFFFu, ss, o);
    }
    __shared__ float rs[8], rss[8];
    int wid = t >> 5, lid = t & 31;
    if (lid == 0) { rs[wid] = s; rss[wid] = ss; }
    __syncthreads();
    s = 0.f; ss = 0.f;
    #pragma unroll
    for (int i = 0; i < 8; i++) { s += rs[i]; ss += rss[i]; }
    float mean = s * (1.0f / DMODEL);
    float var  = (ss - (float)DMODEL * mean * mean) * (1.0f / (DMODEL - 1));
    float inv  = 1.0f / (sqrtf(fmaxf(var, 0.0f)) + LN_EPS);
    const float4 gg = ((const float4*)gamma)[t];
    const float4 bb = ((const float4*)beta)[t];
    float o4[4];
    o4[0] = gg.x * (v.x - mean) * inv + bb.x;
    o4[1] = gg.y * (v.y - mean) * inv + bb.y;
    o4[2] = gg.z * (v.z - mean) * inv + bb.z;
    o4[3] = gg.w * (v.w - mean) * inv + bb.w;
    bf16 hh[4], ll[4];
    #pragma unroll
    for (int j = 0; j < 4; j++) split2(o4[j], hh[j], ll[j]);
    size_t base = (size_t)row * DMODEL + t * 4;
    *(uint2*)(oh + base) = *(uint2*)hh;
    *(uint2*)(ol + base) = *(uint2*)ll;
}

// ---------------- Weight transpose + split: [K,N] fp32 -> [N][K] bf16 hi/lo ----
__global__ void wsplit_tr_kernel(const float* __restrict__ W,
                                 bf16* __restrict__ Th, bf16* __restrict__ Tl,
                                 int K, int N) {
    __shared__ float t[32][33];
    int n0 = blockIdx.x * 32, k0 = blockIdx.y * 32;
    int tx = threadIdx.x, ty = threadIdx.y;   // 32 x 8
    #pragma unroll
    for (int i = 0; i < 4; i++)
        t[ty + 8 * i][tx] = W[(size_t)(k0 + ty + 8 * i) * N + n0 + tx];
    __syncthreads();
    #pragma unroll
    for (int i = 0; i < 4; i++) {
        float f = t[tx][ty + 8 * i];
        bf16 h, l; split2(f, h, l);
        size_t o = (size_t)(n0 + ty + 8 * i) * K + k0 + tx;
        Th[o] = h; Tl[o] = l;
    }
}

// ---------------- V transpose (bf16): [token][DMODEL] -> [b,h,d,s] ----------------
__global__ void vtr_kernel(const bf16* __restrict__ V, bf16* __restrict__ Vt) {
    __shared__ bf16 t[32][33];
    int s0 = blockIdx.x * 32, d0 = blockIdx.y * 32, z = blockIdx.z;  // z = b*16+h
    int bq = z >> 4, hq = z & 15;
    int tx = threadIdx.x, ty = threadIdx.y;    // 32 x 8
    #pragma unroll
    for (int i = 0; i < 4; i++)
        t[ty + 8 * i][tx] = V[(size_t)(bq * SEQ + s0 + ty + 8 * i) * DMODEL + hq * 64 + d0 + tx];
    __syncthreads();
    #pragma unroll
    for (int i = 0; i < 4; i++)
        Vt[(size_t)(z * 64 + d0 + ty + 8 * i) * SEQ + s0 + tx] = t[tx][ty + 8 * i];
}

// ---------------- common helpers ----------------
__device__ __forceinline__ void cpa16(uint32_t d, const void* s) {
    asm volatile("cp.async.cg.shared.global [%0], [%1], 16;" :: "r"(d), "l"(s));
}
__device__ __forceinline__ void cpcommit() {
    asm volatile("cp.async.commit_group;");
}
template<int W> __device__ __forceinline__ void cpwait() {
    asm volatile("cp.async.wait_group %0;" :: "n"(W));
}
__device__ __forceinline__ void mma16816(float c[4], const unsigned a[4], const unsigned b[2]) {
    asm volatile(
        "mma.sync.aligned.m16n8k16.row.col.f32.bf16.bf16.f32 "
        "{%0,%1,%2,%3}, {%4,%5,%6,%7}, {%8,%9}, {%0,%1,%2,%3};\n"
        : "+f"(c[0]), "+f"(c[1]), "+f"(c[2]), "+f"(c[3])
        : "r"(a[0]), "r"(a[1]), "r"(a[2]), "r"(a[3]), "r"(b[0]), "r"(b[1]));
}

// ---------------- Tensor-core GEMM: R6 tiles, 3-stage cp.async, 1 sync/iter ----
// A(hi/lo): [M][K] bf16 rm. B(hi/lo): [N][K] bf16 (k-contiguous). C = act(A@B^T)+res.
#define BM 128
#define BN 128
#define BK 32
#define SKP 40
#define TILE_B (128 * SKP * 2)      // 10240 B
#define STAGE_B (4 * TILE_B)        // 40960 B
#define NSTG 3

__device__ __forceinline__ void fill_stage(uint32_t sb,
        const bf16* __restrict__ Agh, const bf16* __restrict__ Agl,
        const bf16* __restrict__ Bgh, const bf16* __restrict__ Bgl,
        int row0, int col0, int k0, int K, int tid) {
    int r  = tid >> 1;
    int kb = (tid & 1) * 32;
    size_t aoff = ((size_t)(row0 + r) * K + k0) * 2 + kb;
    size_t boff = ((size_t)(col0 + r) * K + k0) * 2 + kb;
    uint32_t dst = sb + (uint32_t)r * (SKP * 2) + kb;
    cpa16(dst,                   (const char*)Agh + aoff);
    cpa16(dst + 16,              (const char*)Agh + aoff + 16);
    cpa16(dst + TILE_B,          (const char*)Agl + aoff);
    cpa16(dst + TILE_B + 16,     (const char*)Agl + aoff + 16);
    cpa16(dst + 2 * TILE_B,      (const char*)Bgh + boff);
    cpa16(dst + 2 * TILE_B + 16, (const char*)Bgh + boff + 16);
    cpa16(dst + 3 * TILE_B,      (const char*)Bgl + boff);
    cpa16(dst + 3 * TILE_B + 16, (const char*)Bgl + boff + 16);
}

template<bool RELU, bool SPLIT>
__global__ __launch_bounds__(256)
void gemm_mma(const bf16* __restrict__ Agh, const bf16* __restrict__ Agl,
              const bf16* __restrict__ Bgh, const bf16* __restrict__ Bgl,
              const float* __restrict__ bias, const float* __restrict__ res,
              float* __restrict__ C, bf16* __restrict__ Ch, bf16* __restrict__ Cl,
              int M, int N, int K) {
    extern __shared__ bf16 smem[];
    uint32_t sbase = (uint32_t)__cvta_generic_to_shared(smem);
    int tid = threadIdx.x, lane = tid & 31, warp = tid >> 5;
    int g = lane >> 2, tig = lane & 3;
    int m_base = (warp & 1) * 64, n_base = (warp >> 1) * 32;
    int row0 = blockIdx.y * BM, col0 = blockIdx.x * BN;

    float acc[4][4][4];
    #pragma unroll
    for (int mi = 0; mi < 4; mi++)
        #pragma unroll
        for (int ni = 0; ni < 4; ni++)
            #pragma unroll
            for (int r = 0; r < 4; r++) acc[mi][ni][r] = 0.0f;

    int NIT = K >> 5;
    fill_stage(sbase, Agh, Agl, Bgh, Bgl, row0, col0, 0, K, tid);
    cpcommit();
    if (NIT > 1) {
        fill_stage(sbase + STAGE_B, Agh, Agl, Bgh, Bgl, row0, col0, 32, K, tid);
        cpcommit();
    }

    for (int it = 0; it < NIT; ++it) {
        // ensure stage it%3 data has landed (own groups), then make all
        // threads' fills visible AND retire all reads of stage (it+2)%3
        if (it == NIT - 1) cpwait<0>(); else cpwait<1>();
        __syncthreads();
        // prefetch stage (it+2)%3 — safe: every warp passed iteration it-1
        if (it + 2 < NIT) {
            fill_stage(sbase + (uint32_t)(((it + 2) % NSTG) * STAGE_B),
                       Agh, Agl, Bgh, Bgl, row0, col0, (it + 2) << 5, K, tid);
            cpcommit();
        }

        const bf16* st  = smem + (it % NSTG) * (STAGE_B / 2);
        const bf16* Ahs = st;
        const bf16* Als = st + TILE_B / 2;
        const bf16* Bhs = st + 2 * (TILE_B / 2);
        const bf16* Bls = st + 3 * (TILE_B / 2);

        #pragma unroll
        for (int ks = 0; ks < 2; ks++) {
            int kk = ks * 16;
            unsigned a_h[4][4], a_l[4][4], b_h[4][2], b_l[4][2];
            #pragma unroll
            for (int mi = 0; mi < 4; mi++) {
                int r = m_base + mi * 16 + g;
                int base = r * SKP + kk + 2 * tig;
                a_h[mi][0] = *(const unsigned*)(Ahs + base);
                a_h[mi][1] = *(const unsigned*)(Ahs + base + 8 * SKP);
                a_h[mi][2] = *(const unsigned*)(Ahs + base + 8);
                a_h[mi][3] = *(const unsigned*)(Ahs + base + 8 * SKP + 8);
                a_l[mi][0] = *(const unsigned*)(Als + base);
                a_l[mi][1] = *(const unsigned*)(Als + base + 8 * SKP);
                a_l[mi][2] = *(const unsigned*)(Als + base + 8);
                a_l[mi][3] = *(const unsigned*)(Als + base + 8 * SKP + 8);
            }
            #pragma unroll
            for (int ni = 0; ni < 4; ni++) {
                int n = n_base + ni * 8 + g;
                int base = n * SKP + kk + 2 * tig;
                b_h[ni][0] = *(const unsigned*)(Bhs + base);
                b_h[ni][1] = *(const unsigned*)(Bhs + base + 8);
                b_l[ni][0] = *(const unsigned*)(Bls + base);
                b_l[ni][1] = *(const unsigned*)(Bls + base + 8);
            }
            #pragma unroll
            for (int mi = 0; mi < 4; mi++)
                #pragma unroll
                for (int ni = 0; ni < 4; ni++) {
                    mma16816(acc[mi][ni], a_h[mi], b_h[ni]);
                    mma16816(acc[mi][ni], a_h[mi], b_l[ni]);
                    mma16816(acc[mi][ni], a_l[mi], b_h[ni]);
                }
        }
        // no end-of-loop sync: next iteration's top sync covers the hazard
    }

    #pragma unroll
    for (int mi = 0; mi < 4; mi++) {
        #pragma unroll
        for (int ni = 0; ni < 4; ni++) {
            int r = row0 + m_base + mi * 16 + g;
            int c = col0 + n_base + ni * 8 + 2 * tig;
            float2 b2 = make_float2(0.f, 0.f);
            if (bias) b2 = *(const float2*)(bias + c);
            float2 v0, v1;
            v0.x = acc[mi][ni][0] + b2.x; v0.y = acc[mi][ni][1] + b2.y;
            v1.x = acc[mi][ni][2] + b2.x; v1.y = acc[mi][ni][3] + b2.y;
            if (RELU) {
                v0.x = fmaxf(v0.x, 0.f); v0.y = fmaxf(v0.y, 0.f);
                v1.x = fmaxf(v1.x, 0.f); v1.y = fmaxf(v1.y, 0.f);
            }
            if (res) {
                float2 r0 = *(const float2*)(res + (size_t)r * N + c);
                float2 r1 = *(const float2*)(res + (size_t)(r + 8) * N + c);
                v0.x += r0.x; v0.y += r0.y; v1.x += r1.x; v1.y += r1.y;
            }
            if (SPLIT) {
                *(unsigned*)(Ch + (size_t)r * N + c)       = packbf2(v0.x, v0.y);
                *(unsigned*)(Ch + (size_t)(r + 8) * N + c) = packbf2(v1.x, v1.y);
                *(unsigned*)(Cl + (size_t)r * N + c)       = packlo2(v0.x, v0.y);
                *(unsigned*)(Cl + (size_t)(r + 8) * N + c) = packlo2(v1.x, v1.y);
            } else {
                *(float2*)(C + (size_t)r * N + c)       = v0;
                *(float2*)(C + (size_t)(r + 8) * N + c) = v1;
            }
        }
    }
}

// ---------------- MMA flash attention (identical to R6) ----------------
#define AQT 128
#define ASK 72
#define AROWB (ASK * 2)
#define ATILE (64 * AROWB)
#define ASTAGE (4 * ATILE)

__device__ __forceinline__ void attn_fill(uint32_t sb, int stage,
        const bf16* __restrict__ Kh, const bf16* __restrict__ Kl,
        const bf16* __restrict__ Vth, const bf16* __restrict__ Vtl,
        int b, int h, int kt, int tid) {
    int r  = tid >> 2;
    int q4 = (tid & 3) * 32;
    size_t koff = ((size_t)(b * SEQ + kt * 64 + r) * DMODEL + h * 64) * 2 + q4;
    size_t voff = ((size_t)((b * NHEAD + h) * 64 + r) * SEQ + kt * 64) * 2 + q4;
    uint32_t d = sb + stage * ASTAGE + (uint32_t)r * AROWB + q4;
    cpa16(d,                  (const char*)Kh  + koff);
    cpa16(d + 16,             (const char*)Kh  + koff + 16);
    cpa16(d + ATILE,          (const char*)Kl  + koff);
    cpa16(d + ATILE + 16,     (const char*)Kl  + koff + 16);
    cpa16(d + 2 * ATILE,      (const char*)Vth + voff);
    cpa16(d + 2 * ATILE + 16, (const char*)Vth + voff + 16);
    cpa16(d + 3 * ATILE,      (const char*)Vtl + voff);
    cpa16(d + 3 * ATILE + 16, (const char*)Vtl + voff + 16);
}

__global__ __launch_bounds__(256)
void attn_mma_kernel(const bf16* __restrict__ Qh, const bf16* __restrict__ Ql,
                     const bf16* __restrict__ Kh, const bf16* __restrict__ Kl,
                     const bf16* __restrict__ Vth, const bf16* __restrict__ Vtl,
                     bf16* __restrict__ Oh, bf16* __restrict__ Ol) {
    extern __shared__ char smraw[];
    uint32_t sb = (uint32_t)__cvta_generic_to_shared(smraw);
    int b = blockIdx.z, h = blockIdx.y, qb = blockIdx.x * AQT;
    int tid = threadIdx.x, lane = tid & 31, warp = tid >> 5;
    int g = lane >> 2, tig = lane & 3;

    {
        int r = tid >> 1;
        int half = (tid & 1) * 64;
        size_t qoff = ((size_t)(b * SEQ + qb + r) * DMODEL + h * 64) * 2 + half;
        uint32_t d0 = sb + (uint32_t)r * AROWB + half;
        #pragma unroll
        for (int i = 0; i < 4; i++) cpa16(d0 + 16 * i, (const char*)Qh + qoff + 16 * i);
        uint32_t d1 = sb + 2 * ATILE + (uint32_t)r * AROWB + half;
        #pragma unroll
        for (int i = 0; i < 4; i++) cpa16(d1 + 16 * i, (const char*)Ql + qoff + 16 * i);
    }
    cpcommit(); cpwait<0>(); __syncthreads();

    unsigned qfh[4][4], qfl[4][4];
    {
        const bf16* Qs_h = (const bf16*)smraw;
        const bf16* Qs_l = (const bf16*)(smraw + 2 * ATILE);
        int mrow = warp * 16 + g;
        #pragma unroll
        for (int ks = 0; ks < 4; ks++) {
            int base = mrow * ASK + ks * 16 + 2 * tig;
            qfh[ks][0] = *(const unsigned*)(Qs_h + base);
            qfh[ks][1] = *(const unsigned*)(Qs_h + base + 8 * ASK);
            qfh[ks][2] = *(const unsigned*)(Qs_h + base + 8);
            qfh[ks][3] = *(const unsigned*)(Qs_h + base + 8 * ASK + 8);
            qfl[ks][0] = *(const unsigned*)(Qs_l + base);
            qfl[ks][1] = *(const unsigned*)(Qs_l + base + 8 * ASK);
            qfl[ks][2] = *(const unsigned*)(Qs_l + base + 8);
            qfl[ks][3] = *(const unsigned*)(Qs_l + base + 8 * ASK + 8);
        }
    }
    __syncthreads();

    float oacc[8][4];
    #pragma unroll
    for (int nf = 0; nf < 8; nf++)
        #pragma unroll
        for (int c = 0; c < 4; c++) oacc[nf][c] = 0.f;
    float mrow[2] = {-1e30f, -1e30f}, lrow[2] = {0.f, 0.f};

    const int NKT = SEQ / 64;
    attn_fill(sb, 0, Kh, Kl, Vth, Vtl, b, h, 0, tid);
    cpcommit();

    for (int kt = 0; kt < NKT; kt++) {
        if (kt + 1 < NKT) {
            attn_fill(sb, (kt + 1) & 1, Kh, Kl, Vth, Vtl, b, h, kt + 1, tid);
            cpcommit();
            cpwait<1>();
        } else {
            cpwait<0>();
        }
        __syncthreads();

        const bf16* st   = (const bf16*)(smraw + (kt & 1) * ASTAGE);
        const bf16* Ks_h = st;
        const bf16* Ks_l = st + ATILE / 2;
        const bf16* Vs_h = st + 2 * (ATILE / 2);
        const bf16* Vs_l = st + 3 * (ATILE / 2);

        float sacc[8][4];
        #pragma unroll
        for (int nf = 0; nf < 8; nf++)
            #pragma unroll
            for (int c = 0; c < 4; c++) sacc[nf][c] = 0.f;
        #pragma unroll
        for (int ks = 0; ks < 4; ks++) {
            #pragma unroll
            for (int nf = 0; nf < 8; nf++) {
                int n = nf * 8 + g;
                int base = n * ASK + ks * 16 + 2 * tig;
                unsigned bh2[2], bl2[2];
                bh2[0] = *(const unsigned*)(Ks_h + base);
                bh2[1] = *(const unsigned*)(Ks_h + base + 8);
                bl2[0] = *(const unsigned*)(Ks_l + base);
                bl2[1] = *(const unsigned*)(Ks_l + base + 8);
                mma16816(sacc[nf], qfh[ks], bh2);
                mma16816(sacc[nf], qfh[ks], bl2);
                mma16816(sacc[nf], qfl[ks], bh2);
            }
        }

        #pragma unroll
        for (int nf = 0; nf < 8; nf++)
            #pragma unroll
            for (int c = 0; c < 4; c++) sacc[nf][c] *= 0.125f;

        #pragma unroll
        for (int rr = 0; rr < 2; rr++) {
            float rm = -1e30f;
            #pragma unroll
            for (int nf = 0; nf < 8; nf++)
                rm = fmaxf(rm, fmaxf(sacc[nf][2 * rr], sacc[nf][2 * rr + 1]));
            rm = fmaxf(rm, __shfl_xor_sync(0xFFFFFFFFu, rm, 1));
            rm = fmaxf(rm, __shfl_xor_sync(0xFFFFFFFFu, rm, 2));
            float mn = fmaxf(mrow[rr], rm);
            float al = __expf(mrow[rr] - mn);
            mrow[rr] = mn;
            float rs = 0.f;
            #pragma unroll
            for (int nf = 0; nf < 8; nf++) {
                sacc[nf][2 * rr]     = __expf(sacc[nf][2 * rr]     - mn);
                sacc[nf][2 * rr + 1] = __expf(sacc[nf][2 * rr + 1] - mn);
                rs += sacc[nf][2 * rr] + sacc[nf][2 * rr + 1];
            }
            rs += __shfl_xor_sync(0xFFFFFFFFu, rs, 1);
            rs += __shfl_xor_sync(0xFFFFFFFFu, rs, 2);
            lrow[rr] = lrow[rr] * al + rs;
            #pragma unroll
            for (int nf = 0; nf < 8; nf++) {
                oacc[nf][2 * rr]     *= al;
                oacc[nf][2 * rr + 1] *= al;
            }
        }

        #pragma unroll
        for (int ks = 0; ks < 4; ks++) {
            unsigned ph2[4], pl2[4];
            ph2[0] = packbf2(sacc[2 * ks][0],     sacc[2 * ks][1]);
            ph2[1] = packbf2(sacc[2 * ks][2],     sacc[2 * ks][3]);
            ph2[2] = packbf2(sacc[2 * ks + 1][0], sacc[2 * ks + 1][1]);
            ph2[3] = packbf2(sacc[2 * ks + 1][2], sacc[2 * ks + 1][3]);
            pl2[0] = packlo2(sacc[2 * ks][0],     sacc[2 * ks][1]);
            pl2[1] = packlo2(sacc[2 * ks][2],     sacc[2 * ks][3]);
            pl2[2] = packlo2(sacc[2 * ks + 1][0], sacc[2 * ks + 1][1]);
            pl2[3] = packlo2(sacc[2 * ks + 1][2], sacc[2 * ks + 1][3]);
            #pragma unroll
            for (int nf = 0; nf < 8; nf++) {
                int n = nf * 8 + g;
                int base = n * ASK + ks * 16 + 2 * tig;
                unsigned vh2[2], vl2[2];
                vh2[0] = *(const unsigned*)(Vs_h + base);
                vh2[1] = *(const unsigned*)(Vs_h + base + 8);
                vl2[0] = *(const unsigned*)(Vs_l + base);
                vl2[1] = *(const unsigned*)(Vs_l + base + 8);
                mma16816(oacc[nf], ph2, vh2);
                mma16816(oacc[nf], ph2, vl2);
                mma16816(oacc[nf], pl2, vh2);
            }
        }
        __syncthreads();
    }

    #pragma unroll
    for (int rr = 0; rr < 2; rr++) {
        float inv = 1.0f / lrow[rr];
        size_t r_glob = (size_t)(b * SEQ + qb + warp * 16 + g + rr * 8);
        #pragma unroll
        for (int nf = 0; nf < 8; nf++) {
            int col = h * 64 + nf * 8 + 2 * tig;
            float o0 = oacc[nf][2 * rr] * inv;
            float o1 = oacc[nf][2 * rr + 1] * inv;
            *(unsigned*)(Oh + r_glob * DMODEL + col) = packbf2(o0, o1);
            *(unsigned*)(Ol + r_glob * DMODEL + col) = packlo2(o0, o1);
        }
    }
}

// ---------------- launch (identical to R6) ----------------
extern "C" void kernel_launch(void* const* d_in, const int* in_sizes, int n_in,
                              void* d_out, int out_size) {
    const float* x   = (const float*)d_in[0];
    const float* w_q = (const float*)d_in[1];
    const float* w_k = (const float*)d_in[2];
    const float* w_v = (const float*)d_in[3];
    const float* w_o = (const float*)d_in[4];
    const float* w1  = (const float*)d_in[5];
    const float* b1  = (const float*)d_in[6];
    const float* w2  = (const float*)d_in[7];
    const float* b2  = (const float*)d_in[8];
    const float* g1  = (const float*)d_in[9];
    const float* be1 = (const float*)d_in[10];
    const float* g2  = (const float*)d_in[11];
    const float* be2 = (const float*)d_in[12];
    float* out = (float*)d_out;

    float *x1;
    bf16 *lnh, *lnl, *qh, *ql, *kh, *kl, *vh, *vl, *vth, *vtl, *atth, *attl, *ffh, *ffl;
    bf16 *wqh, *wql, *wkh, *wkl, *wvh, *wvl, *woh, *wol, *w1h, *w1l, *w2h, *w2l;
    cudaGetSymbolAddress((void**)&x1,  g_x1);
    cudaGetSymbolAddress((void**)&lnh, g_lnh);  cudaGetSymbolAddress((void**)&lnl, g_lnl);
    cudaGetSymbolAddress((void**)&qh,  g_qh);   cudaGetSymbolAddress((void**)&ql,  g_ql);
    cudaGetSymbolAddress((void**)&kh,  g_kh);   cudaGetSymbolAddress((void**)&kl,  g_kl);
    cudaGetSymbolAddress((void**)&vh,  g_vh);   cudaGetSymbolAddress((void**)&vl,  g_vl);
    cudaGetSymbolAddress((void**)&vth, g_vth);  cudaGetSymbolAddress((void**)&vtl, g_vtl);
    cudaGetSymbolAddress((void**)&atth,g_atth); cudaGetSymbolAddress((void**)&attl,g_attl);
    cudaGetSymbolAddress((void**)&ffh, g_ffh);  cudaGetSymbolAddress((void**)&ffl, g_ffl);
    cudaGetSymbolAddress((void**)&wqh, g_wqh);  cudaGetSymbolAddress((void**)&wql, g_wql);
    cudaGetSymbolAddress((void**)&wkh, g_wkh);  cudaGetSymbolAddress((void**)&wkl, g_wkl);
    cudaGetSymbolAddress((void**)&wvh, g_wvh);  cudaGetSymbolAddress((void**)&wvl, g_wvl);
    cudaGetSymbolAddress((void**)&woh, g_woh);  cudaGetSymbolAddress((void**)&wol, g_wol);
    cudaGetSymbolAddress((void**)&w1h, g_w1h);  cudaGetSymbolAddress((void**)&w1l, g_w1l);
    cudaGetSymbolAddress((void**)&w2h, g_w2h);  cudaGetSymbolAddress((void**)&w2l, g_w2l);

    const int gemm_smem = NSTG * STAGE_B;   // 122880 B
    cudaFuncSetAttribute(gemm_mma<false, false>, cudaFuncAttributeMaxDynamicSharedMemorySize, gemm_smem);
    cudaFuncSetAttribute(gemm_mma<false, true >, cudaFuncAttributeMaxDynamicSharedMemorySize, gemm_smem);
    cudaFuncSetAttribute(gemm_mma<true,  true >, cudaFuncAttributeMaxDynamicSharedMemorySize, gemm_smem);
    const int attn_smem = 2 * ASTAGE;
    cudaFuncSetAttribute(attn_mma_kernel, cudaFuncAttributeMaxDynamicSharedMemorySize, attn_smem);

    dim3 wb(32, 8);
    dim3 gProj(DMODEL / BN, ROWS / BM);
    dim3 gFF1 (FFDIM / BN, ROWS / BM);

    wsplit_tr_kernel<<<dim3(DMODEL/32, DMODEL/32), wb>>>(w_q, wqh, wql, DMODEL, DMODEL);
    wsplit_tr_kernel<<<dim3(DMODEL/32, DMODEL/32), wb>>>(w_k, wkh, wkl, DMODEL, DMODEL);
    wsplit_tr_kernel<<<dim3(DMODEL/32, DMODEL/32), wb>>>(w_v, wvh, wvl, DMODEL, DMODEL);
    wsplit_tr_kernel<<<dim3(DMODEL/32, DMODEL/32), wb>>>(w_o, woh, wol, DMODEL, DMODEL);
    wsplit_tr_kernel<<<dim3(FFDIM/32,  DMODEL/32), wb>>>(w1,  w1h, w1l, DMODEL, FFDIM);
    wsplit_tr_kernel<<<dim3(DMODEL/32, FFDIM/32),  wb>>>(w2,  w2h, w2l, FFDIM, DMODEL);

    // LN1 -> split
    ln_split_kernel<<<ROWS, 256>>>(x, g1, be1, lnh, lnl);
    // QKV projections -> split bf16 outputs
    gemm_mma<false,true><<<gProj, 256, gemm_smem>>>(lnh, lnl, wqh, wql, nullptr, nullptr, nullptr, qh, ql, ROWS, DMODEL, DMODEL);
    gemm_mma<false,true><<<gProj, 256, gemm_smem>>>(lnh, lnl, wkh, wkl, nullptr, nullptr, nullptr, kh, kl, ROWS, DMODEL, DMODEL);
    gemm_mma<false,true><<<gProj, 256, gemm_smem>>>(lnh, lnl, wvh, wvl, nullptr, nullptr, nullptr, vh, vl, ROWS, DMODEL, DMODEL);
    // V transpose to [b,h,d,s]
    vtr_kernel<<<dim3(SEQ/32, 2, 32), wb>>>(vh, vth);
    vtr_kernel<<<dim3(SEQ/32, 2, 32), wb>>>(vl, vtl);
    // MMA attention -> split output
    attn_mma_kernel<<<dim3(SEQ/AQT, NHEAD, 2), 256, attn_smem>>>(qh, ql, kh, kl, vth, vtl, atth, attl);
    // output projection + residual (fp32 out)
    gemm_mma<false,false><<<gProj, 256, gemm_smem>>>(atth, attl, woh, wol, nullptr, x, x1, nullptr, nullptr, ROWS, DMODEL, DMODEL);
    // LN2 -> split
    ln_split_kernel<<<ROWS, 256>>>(x1, g2, be2, lnh, lnl);
    // FFN
    gemm_mma<true, true ><<<gFF1,  256, gemm_smem>>>(lnh, lnl, w1h, w1l, b1, nullptr, nullptr, ffh, ffl, ROWS, FFDIM, DMODEL);
    gemm_mma<false,false><<<gProj, 256, gemm_smem>>>(ffh, ffl, w2h, w2l, b2, x1, out, nullptr, nullptr, ROWS, DMODEL, FFDIM);
}

// round 11
// speedup vs baseline: 1.6317x; 1.0485x over previous
#include <cuda_runtime.h>
#include <cuda_bf16.h>
#include <math.h>
#include <stdint.h>

#define DMODEL 1024
#define NHEAD  16
#define FFDIM  4096
#define ROWS   4096      // B*S
#define SEQ    2048
#define QKVW   3072      // packed qkv width
#define LN_EPS 1e-6f

typedef __nv_bfloat16 bf16;

// ---------------- scratch (no allocation allowed) ----------------
__device__ float g_x1[ROWS * DMODEL];

__device__ bf16 g_lnh  [ROWS * DMODEL],   g_lnl  [ROWS * DMODEL];
__device__ bf16 g_qkvh [ROWS * QKVW],     g_qkvl [ROWS * QKVW];    // [row][q|k|v]
__device__ bf16 g_vth  [ROWS * DMODEL],   g_vtl  [ROWS * DMODEL];  // [b,h,d,s]
__device__ bf16 g_atth [ROWS * DMODEL],   g_attl [ROWS * DMODEL];
__device__ bf16 g_ffh  [ROWS * FFDIM],    g_ffl  [ROWS * FFDIM];
__device__ bf16 g_wqkvh[QKVW * DMODEL],   g_wqkvl[QKVW * DMODEL];  // [n][k]
__device__ bf16 g_woh  [DMODEL * DMODEL], g_wol  [DMODEL * DMODEL];
__device__ bf16 g_w1h  [DMODEL * FFDIM],  g_w1l  [DMODEL * FFDIM];
__device__ bf16 g_w2h  [FFDIM * DMODEL],  g_w2l  [FFDIM * DMODEL];

__device__ __forceinline__ void split2(float f, bf16& h, bf16& l) {
    h = __float2bfloat16_rn(f);
    l = __float2bfloat16_rn(f - __bfloat162float(h));
}
__device__ __forceinline__ unsigned packbf2(float a, float b) {
    __nv_bfloat162 t;
    t.x = __float2bfloat16_rn(a);
    t.y = __float2bfloat16_rn(b);
    return *(unsigned*)&t;
}
__device__ __forceinline__ unsigned packlo2(float a, float b) {
    __nv_bfloat162 t;
    t.x = __float2bfloat16_rn(a - __bfloat162float(__float2bfloat16_rn(a)));
    t.y = __float2bfloat16_rn(b - __bfloat162float(__float2bfloat16_rn(b)));
    return *(unsigned*)&t;
}

// ---------------- LayerNorm -> bf16 hi/lo split output ----------------
__global__ void ln_split_kernel(const float* __restrict__ x,
                                const float* __restrict__ gamma,
                                const float* __restrict__ beta,
                                bf16* __restrict__ oh, bf16* __restrict__ ol) {
    int row = blockIdx.x;
    int t = threadIdx.x;
    const float4* xr = (const float4*)(x + (size_t)row * DMODEL);
    float4 v = xr[t];
    float s  = v.x + v.y + v.z + v.w;
    float ss = v.x * v.x + v.y * v.y + v.z * v.z + v.w * v.w;
    #pragma unroll
    for (int o = 16; o > 0; o >>= 1) {
        s  += __shfl_xor_sync(0xFFFFFFFFu, s,  o);
        ss += __shfl_xor_sync(0xFFFFFFFFu, ss, o);
    }
    __shared__ float rs[8], rss[8];
    int wid = t >> 5, lid = t & 31;
    if (lid == 0) { rs[wid] = s; rss[wid] = ss; }
    __syncthreads();
    s = 0.f; ss = 0.f;
    #pragma unroll
    for (int i = 0; i < 8; i++) { s += rs[i]; ss += rss[i]; }
    float mean = s * (1.0f / DMODEL);
    float var  = (ss - (float)DMODEL * mean * mean) * (1.0f / (DMODEL - 1));
    float inv  = 1.0f / (sqrtf(fmaxf(var, 0.0f)) + LN_EPS);
    const float4 gg = ((const float4*)gamma)[t];
    const float4 bb = ((const float4*)beta)[t];
    float o4[4];
    o4[0] = gg.x * (v.x - mean) * inv + bb.x;
    o4[1] = gg.y * (v.y - mean) * inv + bb.y;
    o4[2] = gg.z * (v.z - mean) * inv + bb.z;
    o4[3] = gg.w * (v.w - mean) * inv + bb.w;
    bf16 hh[4], ll[4];
    #pragma unroll
    for (int j = 0; j < 4; j++) split2(o4[j], hh[j], ll[j]);
    size_t base = (size_t)row * DMODEL + t * 4;
    *(uint2*)(oh + base) = *(uint2*)hh;
    *(uint2*)(ol + base) = *(uint2*)ll;
}

// ---------------- Weight transpose + split: [K,N] fp32 -> [N][K] bf16 hi/lo ----
__global__ void wsplit_tr_kernel(const float* __restrict__ W,
                                 bf16* __restrict__ Th, bf16* __restrict__ Tl,
                                 int K, int N) {
    __shared__ float t[32][33];
    int n0 = blockIdx.x * 32, k0 = blockIdx.y * 32;
    int tx = threadIdx.x, ty = threadIdx.y;   // 32 x 8
    #pragma unroll
    for (int i = 0; i < 4; i++)
        t[ty + 8 * i][tx] = W[(size_t)(k0 + ty + 8 * i) * N + n0 + tx];
    __syncthreads();
    #pragma unroll
    for (int i = 0; i < 4; i++) {
        float f = t[tx][ty + 8 * i];
        bf16 h, l; split2(f, h, l);
        size_t o = (size_t)(n0 + ty + 8 * i) * K + k0 + tx;
        Th[o] = h; Tl[o] = l;
    }
}

// ---------------- V transpose: packed qkv [row][3072] col 2048+ -> [b,h,d,s] ----
__global__ void vtr_kernel(const bf16* __restrict__ V, bf16* __restrict__ Vt) {
    __shared__ bf16 t[32][33];
    int s0 = blockIdx.x * 32, d0 = blockIdx.y * 32, z = blockIdx.z;  // z = b*16+h
    int bq = z >> 4, hq = z & 15;
    int tx = threadIdx.x, ty = threadIdx.y;    // 32 x 8
    #pragma unroll
    for (int i = 0; i < 4; i++)
        t[ty + 8 * i][tx] = V[(size_t)(bq * SEQ + s0 + ty + 8 * i) * QKVW + 2048 + hq * 64 + d0 + tx];
    __syncthreads();
    #pragma unroll
    for (int i = 0; i < 4; i++)
        Vt[(size_t)(z * 64 + d0 + ty + 8 * i) * SEQ + s0 + tx] = t[tx][ty + 8 * i];
}

// ---------------- common helpers ----------------
__device__ __forceinline__ void cpa16(uint32_t d, const void* s) {
    asm volatile("cp.async.cg.shared.global [%0], [%1], 16;" :: "r"(d), "l"(s));
}
__device__ __forceinline__ void cpcommit() {
    asm volatile("cp.async.commit_group;");
}
template<int W> __device__ __forceinline__ void cpwait() {
    asm volatile("cp.async.wait_group %0;" :: "n"(W));
}
__device__ __forceinline__ void mma16816(float c[4], const unsigned a[4], const unsigned b[2]) {
    asm volatile(
        "mma.sync.aligned.m16n8k16.row.col.f32.bf16.bf16.f32 "
        "{%0,%1,%2,%3}, {%4,%5,%6,%7}, {%8,%9}, {%0,%1,%2,%3};\n"
        : "+f"(c[0]), "+f"(c[1]), "+f"(c[2]), "+f"(c[3])
        : "r"(a[0]), "r"(a[1]), "r"(a[2]), "r"(a[3]), "r"(b[0]), "r"(b[1]));
}

// ---------------- Tensor-core GEMM: EXACT R6 structure (2-stage, 2 syncs) ------
// A(hi/lo): [M][K] bf16 rm. B(hi/lo): [N][K] bf16 (k-contiguous). C = act(A@B^T)+res.
#define BM 128
#define BN 128
#define BK 32
#define SKP 40
#define TILE_B (128 * SKP * 2)      // 10240 B
#define STAGE_B (4 * TILE_B)        // 40960 B

__device__ __forceinline__ void fill_stage(uint32_t sb,
        const bf16* __restrict__ Agh, const bf16* __restrict__ Agl,
        const bf16* __restrict__ Bgh, const bf16* __restrict__ Bgl,
        int row0, int col0, int k0, int K, int tid) {
    int r  = tid >> 1;
    int kb = (tid & 1) * 32;
    size_t aoff = ((size_t)(row0 + r) * K + k0) * 2 + kb;
    size_t boff = ((size_t)(col0 + r) * K + k0) * 2 + kb;
    uint32_t dst = sb + (uint32_t)r * (SKP * 2) + kb;
    cpa16(dst,                   (const char*)Agh + aoff);
    cpa16(dst + 16,              (const char*)Agh + aoff + 16);
    cpa16(dst + TILE_B,          (const char*)Agl + aoff);
    cpa16(dst + TILE_B + 16,     (const char*)Agl + aoff + 16);
    cpa16(dst + 2 * TILE_B,      (const char*)Bgh + boff);
    cpa16(dst + 2 * TILE_B + 16, (const char*)Bgh + boff + 16);
    cpa16(dst + 3 * TILE_B,      (const char*)Bgl + boff);
    cpa16(dst + 3 * TILE_B + 16, (const char*)Bgl + boff + 16);
}

template<bool RELU, bool SPLIT>
__global__ __launch_bounds__(256)
void gemm_mma(const bf16* __restrict__ Agh, const bf16* __restrict__ Agl,
              const bf16* __restrict__ Bgh, const bf16* __restrict__ Bgl,
              const float* __restrict__ bias, const float* __restrict__ res,
              float* __restrict__ C, bf16* __restrict__ Ch, bf16* __restrict__ Cl,
              int M, int N, int K) {
    extern __shared__ bf16 smem[];
    uint32_t sbase = (uint32_t)__cvta_generic_to_shared(smem);
    int tid = threadIdx.x, lane = tid & 31, warp = tid >> 5;
    int g = lane >> 2, tig = lane & 3;
    int m_base = (warp & 1) * 64, n_base = (warp >> 1) * 32;
    int row0 = blockIdx.y * BM, col0 = blockIdx.x * BN;

    float acc[4][4][4];
    #pragma unroll
    for (int mi = 0; mi < 4; mi++)
        #pragma unroll
        for (int ni = 0; ni < 4; ni++)
            #pragma unroll
            for (int r = 0; r < 4; r++) acc[mi][ni][r] = 0.0f;

    int NIT = K >> 5;
    fill_stage(sbase, Agh, Agl, Bgh, Bgl, row0, col0, 0, K, tid);
    cpcommit();

    for (int it = 0; it < NIT; ++it) {
        if (it + 1 < NIT) {
            fill_stage(sbase + ((it + 1) & 1) * STAGE_B, Agh, Agl, Bgh, Bgl,
                       row0, col0, (it + 1) << 5, K, tid);
            cpcommit();
            cpwait<1>();
        } else {
            cpwait<0>();
        }
        __syncthreads();

        const bf16* st  = smem + (it & 1) * (STAGE_B / 2);
        const bf16* Ahs = st;
        const bf16* Als = st + TILE_B / 2;
        const bf16* Bhs = st + 2 * (TILE_B / 2);
        const bf16* Bls = st + 3 * (TILE_B / 2);

        #pragma unroll
        for (int ks = 0; ks < 2; ks++) {
            int kk = ks * 16;
            unsigned a_h[4][4], a_l[4][4], b_h[4][2], b_l[4][2];
            #pragma unroll
            for (int mi = 0; mi < 4; mi++) {
                int r = m_base + mi * 16 + g;
                int base = r * SKP + kk + 2 * tig;
                a_h[mi][0] = *(const unsigned*)(Ahs + base);
                a_h[mi][1] = *(const unsigned*)(Ahs + base + 8 * SKP);
                a_h[mi][2] = *(const unsigned*)(Ahs + base + 8);
                a_h[mi][3] = *(const unsigned*)(Ahs + base + 8 * SKP + 8);
                a_l[mi][0] = *(const unsigned*)(Als + base);
                a_l[mi][1] = *(const unsigned*)(Als + base + 8 * SKP);
                a_l[mi][2] = *(const unsigned*)(Als + base + 8);
                a_l[mi][3] = *(const unsigned*)(Als + base + 8 * SKP + 8);
            }
            #pragma unroll
            for (int ni = 0; ni < 4; ni++) {
                int n = n_base + ni * 8 + g;
                int base = n * SKP + kk + 2 * tig;
                b_h[ni][0] = *(const unsigned*)(Bhs + base);
                b_h[ni][1] = *(const unsigned*)(Bhs + base + 8);
                b_l[ni][0] = *(const unsigned*)(Bls + base);
                b_l[ni][1] = *(const unsigned*)(Bls + base + 8);
            }
            #pragma unroll
            for (int mi = 0; mi < 4; mi++)
                #pragma unroll
                for (int ni = 0; ni < 4; ni++) {
                    mma16816(acc[mi][ni], a_h[mi], b_h[ni]);
                    mma16816(acc[mi][ni], a_h[mi], b_l[ni]);
                    mma16816(acc[mi][ni], a_l[mi], b_h[ni]);
                }
        }
        __syncthreads();
    }

    #pragma unroll
    for (int mi = 0; mi < 4; mi++) {
        #pragma unroll
        for (int ni = 0; ni < 4; ni++) {
            int r = row0 + m_base + mi * 16 + g;
            int c = col0 + n_base + ni * 8 + 2 * tig;
            float2 b2 = make_float2(0.f, 0.f);
            if (bias) b2 = *(const float2*)(bias + c);
            float2 v0, v1;
            v0.x = acc[mi][ni][0] + b2.x; v0.y = acc[mi][ni][1] + b2.y;
            v1.x = acc[mi][ni][2] + b2.x; v1.y = acc[mi][ni][3] + b2.y;
            if (RELU) {
                v0.x = fmaxf(v0.x, 0.f); v0.y = fmaxf(v0.y, 0.f);
                v1.x = fmaxf(v1.x, 0.f); v1.y = fmaxf(v1.y, 0.f);
            }
            if (res) {
                float2 r0 = *(const float2*)(res + (size_t)r * N + c);
                float2 r1 = *(const float2*)(res + (size_t)(r + 8) * N + c);
                v0.x += r0.x; v0.y += r0.y; v1.x += r1.x; v1.y += r1.y;
            }
            if (SPLIT) {
                *(unsigned*)(Ch + (size_t)r * N + c)       = packbf2(v0.x, v0.y);
                *(unsigned*)(Ch + (size_t)(r + 8) * N + c) = packbf2(v1.x, v1.y);
                *(unsigned*)(Cl + (size_t)r * N + c)       = packlo2(v0.x, v0.y);
                *(unsigned*)(Cl + (size_t)(r + 8) * N + c) = packlo2(v1.x, v1.y);
            } else {
                *(float2*)(C + (size_t)r * N + c)       = v0;
                *(float2*)(C + (size_t)(r + 8) * N + c) = v1;
            }
        }
    }
}

// ---------------- MMA flash attention (R6 structure; packed QKV input) ----------
#define AQT 128
#define ASK 72
#define AROWB (ASK * 2)
#define ATILE (64 * AROWB)
#define ASTAGE (4 * ATILE)

__device__ __forceinline__ void attn_fill(uint32_t sb, int stage,
        const bf16* __restrict__ QKVh, const bf16* __restrict__ QKVl,
        const bf16* __restrict__ Vth, const bf16* __restrict__ Vtl,
        int b, int h, int kt, int tid) {
    int r  = tid >> 2;
    int q4 = (tid & 3) * 32;
    size_t koff = ((size_t)(b * SEQ + kt * 64 + r) * QKVW + 1024 + h * 64) * 2 + q4;
    size_t voff = ((size_t)((b * NHEAD + h) * 64 + r) * SEQ + kt * 64) * 2 + q4;
    uint32_t d = sb + stage * ASTAGE + (uint32_t)r * AROWB + q4;
    cpa16(d,                  (const char*)QKVh + koff);
    cpa16(d + 16,             (const char*)QKVh + koff + 16);
    cpa16(d + ATILE,          (const char*)QKVl + koff);
    cpa16(d + ATILE + 16,     (const char*)QKVl + koff + 16);
    cpa16(d + 2 * ATILE,      (const char*)Vth + voff);
    cpa16(d + 2 * ATILE + 16, (const char*)Vth + voff + 16);
    cpa16(d + 3 * ATILE,      (const char*)Vtl + voff);
    cpa16(d + 3 * ATILE + 16, (const char*)Vtl + voff + 16);
}

__global__ __launch_bounds__(256)
void attn_mma_kernel(const bf16* __restrict__ QKVh, const bf16* __restrict__ QKVl,
                     const bf16* __restrict__ Vth, const bf16* __restrict__ Vtl,
                     bf16* __restrict__ Oh, bf16* __restrict__ Ol) {
    extern __shared__ char smraw[];
    uint32_t sb = (uint32_t)__cvta_generic_to_shared(smraw);
    int b = blockIdx.z, h = blockIdx.y, qb = blockIdx.x * AQT;
    int tid = threadIdx.x, lane = tid & 31, warp = tid >> 5;
    int g = lane >> 2, tig = lane & 3;

    {   // stage Q tile (128 x 64) hi/lo from packed cols [0,1024)
        int r = tid >> 1;
        int half = (tid & 1) * 64;
        size_t qoff = ((size_t)(b * SEQ + qb + r) * QKVW + h * 64) * 2 + half;
        uint32_t d0 = sb + (uint32_t)r * AROWB + half;
        #pragma unroll
        for (int i = 0; i < 4; i++) cpa16(d0 + 16 * i, (const char*)QKVh + qoff + 16 * i);
        uint32_t d1 = sb + 2 * ATILE + (uint32_t)r * AROWB + half;
        #pragma unroll
        for (int i = 0; i < 4; i++) cpa16(d1 + 16 * i, (const char*)QKVl + qoff + 16 * i);
    }
    cpcommit(); cpwait<0>(); __syncthreads();

    unsigned qfh[4][4], qfl[4][4];
    {
        const bf16* Qs_h = (const bf16*)smraw;
        const bf16* Qs_l = (const bf16*)(smraw + 2 * ATILE);
        int mrow = warp * 16 + g;
        #pragma unroll
        for (int ks = 0; ks < 4; ks++) {
            int base = mrow * ASK + ks * 16 + 2 * tig;
            qfh[ks][0] = *(const unsigned*)(Qs_h + base);
            qfh[ks][1] = *(const unsigned*)(Qs_h + base + 8 * ASK);
            qfh[ks][2] = *(const unsigned*)(Qs_h + base + 8);
            qfh[ks][3] = *(const unsigned*)(Qs_h + base + 8 * ASK + 8);
            qfl[ks][0] = *(const unsigned*)(Qs_l + base);
            qfl[ks][1] = *(const unsigned*)(Qs_l + base + 8 * ASK);
            qfl[ks][2] = *(const unsigned*)(Qs_l + base + 8);
            qfl[ks][3] = *(const unsigned*)(Qs_l + base + 8 * ASK + 8);
        }
    }
    __syncthreads();

    float oacc[8][4];
    #pragma unroll
    for (int nf = 0; nf < 8; nf++)
        #pragma unroll
        for (int c = 0; c < 4; c++) oacc[nf][c] = 0.f;
    float mrow[2] = {-1e30f, -1e30f}, lrow[2] = {0.f, 0.f};

    const int NKT = SEQ / 64;
    attn_fill(sb, 0, QKVh, QKVl, Vth, Vtl, b, h, 0, tid);
    cpcommit();

    for (int kt = 0; kt < NKT; kt++) {
        if (kt + 1 < NKT) {
            attn_fill(sb, (kt + 1) & 1, QKVh, QKVl, Vth, Vtl, b, h, kt + 1, tid);
            cpcommit();
            cpwait<1>();
        } else {
            cpwait<0>();
        }
        __syncthreads();

        const bf16* st   = (const bf16*)(smraw + (kt & 1) * ASTAGE);
        const bf16* Ks_h = st;
        const bf16* Ks_l = st + ATILE / 2;
        const bf16* Vs_h = st + 2 * (ATILE / 2);
        const bf16* Vs_l = st + 3 * (ATILE / 2);

        float sacc[8][4];
        #pragma unroll
        for (int nf = 0; nf < 8; nf++)
            #pragma unroll
            for (int c = 0; c < 4; c++) sacc[nf][c] = 0.f;
        #pragma unroll
        for (int ks = 0; ks < 4; ks++) {
            #pragma unroll
            for (int nf = 0; nf < 8; nf++) {
                int n = nf * 8 + g;
                int base = n * ASK + ks * 16 + 2 * tig;
                unsigned bh2[2], bl2[2];
                bh2[0] = *(const unsigned*)(Ks_h + base);
                bh2[1] = *(const unsigned*)(Ks_h + base + 8);
                bl2[0] = *(const unsigned*)(Ks_l + base);
                bl2[1] = *(const unsigned*)(Ks_l + base + 8);
                mma16816(sacc[nf], qfh[ks], bh2);
                mma16816(sacc[nf], qfh[ks], bl2);
                mma16816(sacc[nf], qfl[ks], bh2);
            }
        }

        #pragma unroll
        for (int nf = 0; nf < 8; nf++)
            #pragma unroll
            for (int c = 0; c < 4; c++) sacc[nf][c] *= 0.125f;

        #pragma unroll
        for (int rr = 0; rr < 2; rr++) {
            float rm = -1e30f;
            #pragma unroll
            for (int nf = 0; nf < 8; nf++)
                rm = fmaxf(rm, fmaxf(sacc[nf][2 * rr], sacc[nf][2 * rr + 1]));
            rm = fmaxf(rm, __shfl_xor_sync(0xFFFFFFFFu, rm, 1));
            rm = fmaxf(rm, __shfl_xor_sync(0xFFFFFFFFu, rm, 2));
            float mn = fmaxf(mrow[rr], rm);
            float al = __expf(mrow[rr] - mn);
            mrow[rr] = mn;
            float rs = 0.f;
            #pragma unroll
            for (int nf = 0; nf < 8; nf++) {
                sacc[nf][2 * rr]     = __expf(sacc[nf][2 * rr]     - mn);
                sacc[nf][2 * rr + 1] = __expf(sacc[nf][2 * rr + 1] - mn);
                rs += sacc[nf][2 * rr] + sacc[nf][2 * rr + 1];
            }
            rs += __shfl_xor_sync(0xFFFFFFFFu, rs, 1);
            rs += __shfl_xor_sync(0xFFFFFFFFu, rs, 2);
            lrow[rr] = lrow[rr] * al + rs;
            #pragma unroll
            for (int nf = 0; nf < 8; nf++) {
                oacc[nf][2 * rr]     *= al;
                oacc[nf][2 * rr + 1] *= al;
            }
        }

        #pragma unroll
        for (int ks = 0; ks < 4; ks++) {
            unsigned ph2[4], pl2[4];
            ph2[0] = packbf2(sacc[2 * ks][0],     sacc[2 * ks][1]);
            ph2[1] = packbf2(sacc[2 * ks][2],     sacc[2 * ks][3]);
            ph2[2] = packbf2(sacc[2 * ks + 1][0], sacc[2 * ks + 1][1]);
            ph2[3] = packbf2(sacc[2 * ks + 1][2], sacc[2 * ks + 1][3]);
            pl2[0] = packlo2(sacc[2 * ks][0],     sacc[2 * ks][1]);
            pl2[1] = packlo2(sacc[2 * ks][2],     sacc[2 * ks][3]);
            pl2[2] = packlo2(sacc[2 * ks + 1][0], sacc[2 * ks + 1][1]);
            pl2[3] = packlo2(sacc[2 * ks + 1][2], sacc[2 * ks + 1][3]);
            #pragma unroll
            for (int nf = 0; nf < 8; nf++) {
                int n = nf * 8 + g;
                int base = n * ASK + ks * 16 + 2 * tig;
                unsigned vh2[2], vl2[2];
                vh2[0] = *(const unsigned*)(Vs_h + base);
                vh2[1] = *(const unsigned*)(Vs_h + base + 8);
                vl2[0] = *(const unsigned*)(Vs_l + base);
                vl2[1] = *(const unsigned*)(Vs_l + base + 8);
                mma16816(oacc[nf], ph2, vh2);
                mma16816(oacc[nf], ph2, vl2);
                mma16816(oacc[nf], pl2, vh2);
            }
        }
        __syncthreads();
    }

    #pragma unroll
    for (int rr = 0; rr < 2; rr++) {
        float inv = 1.0f / lrow[rr];
        size_t r_glob = (size_t)(b * SEQ + qb + warp * 16 + g + rr * 8);
        #pragma unroll
        for (int nf = 0; nf < 8; nf++) {
            int col = h * 64 + nf * 8 + 2 * tig;
            float o0 = oacc[nf][2 * rr] * inv;
            float o1 = oacc[nf][2 * rr + 1] * inv;
            *(unsigned*)(Oh + r_glob * DMODEL + col) = packbf2(o0, o1);
            *(unsigned*)(Ol + r_glob * DMODEL + col) = packlo2(o0, o1);
        }
    }
}

// ---------------- launch ----------------
extern "C" void kernel_launch(void* const* d_in, const int* in_sizes, int n_in,
                              void* d_out, int out_size) {
    const float* x   = (const float*)d_in[0];
    const float* w_q = (const float*)d_in[1];
    const float* w_k = (const float*)d_in[2];
    const float* w_v = (const float*)d_in[3];
    const float* w_o = (const float*)d_in[4];
    const float* w1  = (const float*)d_in[5];
    const float* b1  = (const float*)d_in[6];
    const float* w2  = (const float*)d_in[7];
    const float* b2  = (const float*)d_in[8];
    const float* g1  = (const float*)d_in[9];
    const float* be1 = (const float*)d_in[10];
    const float* g2  = (const float*)d_in[11];
    const float* be2 = (const float*)d_in[12];
    float* out = (float*)d_out;

    float *x1;
    bf16 *lnh, *lnl, *qkvh, *qkvl, *vth, *vtl, *atth, *attl, *ffh, *ffl;
    bf16 *wqkvh, *wqkvl, *woh, *wol, *w1h, *w1l, *w2h, *w2l;
    cudaGetSymbolAddress((void**)&x1,    g_x1);
    cudaGetSymbolAddress((void**)&lnh,   g_lnh);   cudaGetSymbolAddress((void**)&lnl,   g_lnl);
    cudaGetSymbolAddress((void**)&qkvh,  g_qkvh);  cudaGetSymbolAddress((void**)&qkvl,  g_qkvl);
    cudaGetSymbolAddress((void**)&vth,   g_vth);   cudaGetSymbolAddress((void**)&vtl,   g_vtl);
    cudaGetSymbolAddress((void**)&atth,  g_atth);  cudaGetSymbolAddress((void**)&attl,  g_attl);
    cudaGetSymbolAddress((void**)&ffh,   g_ffh);   cudaGetSymbolAddress((void**)&ffl,   g_ffl);
    cudaGetSymbolAddress((void**)&wqkvh, g_wqkvh); cudaGetSymbolAddress((void**)&wqkvl, g_wqkvl);
    cudaGetSymbolAddress((void**)&woh,   g_woh);   cudaGetSymbolAddress((void**)&wol,   g_wol);
    cudaGetSymbolAddress((void**)&w1h,   g_w1h);   cudaGetSymbolAddress((void**)&w1l,   g_w1l);
    cudaGetSymbolAddress((void**)&w2h,   g_w2h);   cudaGetSymbolAddress((void**)&w2l,   g_w2l);

    const int gemm_smem = 2 * STAGE_B;   // 81920 B (R6 value)
    cudaFuncSetAttribute(gemm_mma<false, false>, cudaFuncAttributeMaxDynamicSharedMemorySize, gemm_smem);
    cudaFuncSetAttribute(gemm_mma<false, true >, cudaFuncAttributeMaxDynamicSharedMemorySize, gemm_smem);
    cudaFuncSetAttribute(gemm_mma<true,  true >, cudaFuncAttributeMaxDynamicSharedMemorySize, gemm_smem);
    const int attn_smem = 2 * ASTAGE;
    cudaFuncSetAttribute(attn_mma_kernel, cudaFuncAttributeMaxDynamicSharedMemorySize, attn_smem);

    dim3 wb(32, 8);
    dim3 gQKV (QKVW / BN, ROWS / BM);    // 24 x 32 = 768 CTAs
    dim3 gProj(DMODEL / BN, ROWS / BM);  // 8 x 32
    dim3 gFF1 (FFDIM / BN, ROWS / BM);   // 32 x 32

    // launch 0: LN1
    ln_split_kernel<<<ROWS, 256>>>(x, g1, be1, lnh, lnl);
    // launches 1-4: weight splits needed before QKV gemm
    wsplit_tr_kernel<<<dim3(DMODEL/32, DMODEL/32), wb>>>(w_q, wqkvh,                 wqkvl,                 DMODEL, DMODEL);
    wsplit_tr_kernel<<<dim3(DMODEL/32, DMODEL/32), wb>>>(w_k, wqkvh + 1024 * DMODEL, wqkvl + 1024 * DMODEL, DMODEL, DMODEL);
    wsplit_tr_kernel<<<dim3(DMODEL/32, DMODEL/32), wb>>>(w_v, wqkvh + 2048 * DMODEL, wqkvl + 2048 * DMODEL, DMODEL, DMODEL);
    wsplit_tr_kernel<<<dim3(DMODEL/32, DMODEL/32), wb>>>(w_o, woh, wol, DMODEL, DMODEL);
    // launch 5: fused QKV GEMM  (<- ncu -s 5 -c 1 profiles this)
    gemm_mma<false,true><<<gQKV, 256, gemm_smem>>>(lnh, lnl, wqkvh, wqkvl, nullptr, nullptr, nullptr, qkvh, qkvl, ROWS, QKVW, DMODEL);
    // remaining weight preps
    wsplit_tr_kernel<<<dim3(FFDIM/32,  DMODEL/32), wb>>>(w1, w1h, w1l, DMODEL, FFDIM);
    wsplit_tr_kernel<<<dim3(DMODEL/32, FFDIM/32),  wb>>>(w2, w2h, w2l, FFDIM, DMODEL);
    // V transpose to [b,h,d,s] (reads packed v block)
    vtr_kernel<<<dim3(SEQ/32, 2, 32), wb>>>(qkvh, vth);
    vtr_kernel<<<dim3(SEQ/32, 2, 32), wb>>>(qkvl, vtl);
    // MMA attention -> split output
    attn_mma_kernel<<<dim3(SEQ/AQT, NHEAD, 2), 256, attn_smem>>>(qkvh, qkvl, vth, vtl, atth, attl);
    // output projection + residual (fp32 out)
    gemm_mma<false,false><<<gProj, 256, gemm_smem>>>(atth, attl, woh, wol, nullptr, x, x1, nullptr, nullptr, ROWS, DMODEL, DMODEL);
    // LN2 -> split
    ln_split_kernel<<<ROWS, 256>>>(x1, g2, be2, lnh, lnl);
    // FFN
    gemm_mma<true, true ><<<gFF1,  256, gemm_smem>>>(lnh, lnl, w1h, w1l, b1, nullptr, nullptr, ffh, ffl, ROWS, FFDIM, DMODEL);
    gemm_mma<false,false><<<gProj, 256, gemm_smem>>>(ffh, ffl, w2h, w2l, b2, x1, out, nullptr, nullptr, ROWS, DMODEL, FFDIM);
}